// round 16
// baseline (speedup 1.0000x reference)
#include <cuda_runtime.h>
#include <cuda_bf16.h>
#include <cuda_fp8.h>
#include <cstdint>

// ============================================================================
// Base-ISA helpers
// ============================================================================

__device__ __forceinline__ uint32_t smem_to_u32(const void* smem_ptr) {
    uint32_t addr;
    asm("{ .reg .u64 tmp; cvta.to.shared.u64 tmp, %1; cvt.u32.u64 %0, tmp; }"
        : "=r"(addr) : "l"(smem_ptr));
    return addr;
}

#define CP_ASYNC_16(dst_u32, src_ptr) \
    asm volatile("cp.async.cg.shared.global [%0], [%1], 16;\n" \
                 :: "r"(dst_u32), "l"(src_ptr))

#define CP_COMMIT() asm volatile("cp.async.commit_group;\n" ::: "memory")

#define CP_WAIT(n)  asm volatile("cp.async.wait_group %0;\n" :: "n"(n) : "memory")

#define LDMATRIX_X4(r0, r1, r2, r3, addr) \
    asm volatile("ldmatrix.sync.aligned.m8n8.x4.shared.b16 {%0,%1,%2,%3}, [%4];\n" \
                 : "=r"(r0), "=r"(r1), "=r"(r2), "=r"(r3) : "r"(addr))

__device__ __forceinline__ void mma_e4m3(
    float& d0, float& d1, float& d2, float& d3,
    uint32_t a0, uint32_t a1, uint32_t a2, uint32_t a3,
    uint32_t b0, uint32_t b1)
{
    asm volatile(
        "mma.sync.aligned.m16n8k32.row.col.f32.e4m3.e4m3.f32 "
        "{%0,%1,%2,%3}, {%4,%5,%6,%7}, {%8,%9}, {%0,%1,%2,%3};\n"
        : "+f"(d0), "+f"(d1), "+f"(d2), "+f"(d3)
        : "r"(a0), "r"(a1), "r"(a2), "r"(a3), "r"(b0), "r"(b1));
}

// ============================================================================
// Problem constants & scratch
// ============================================================================

static constexpr int K_DIM = 4096;
static constexpr int N_DIM = 4096;
static constexpr int M_MAX = 8192;

__device__ uint4 g_xq4[(size_t)M_MAX * K_DIM / 16];   // 32 MB fp8 x
__device__ uint4 g_wq4[(size_t)N_DIM * K_DIM / 16];   // 16 MB fp8 w

__device__ unsigned g_amax_bits[2];
__device__ float g_combined;

__device__ __forceinline__ float scale_from_bits(unsigned bits) {
    float a = fmaxf(__uint_as_float(bits), 1e-12f);
    return 448.0f / a;
}

// ============================================================================
// Pre-pass kernels (R13 config — measured at the traffic floor)
// ============================================================================

__global__ void absmax_all_kernel(const float4* __restrict__ x, int nx16,
                                  const float4* __restrict__ w, int nw16,
                                  int xb) {
    const bool isX = (int)blockIdx.x < xb;
    const float4* p = isX ? x : w;
    const int n16 = isX ? nx16 : nw16;
    const int nb = isX ? xb : (gridDim.x - xb);
    const int b0 = isX ? (int)blockIdx.x : (int)blockIdx.x - xb;

    float m0 = 0.0f, m1 = 0.0f, m2 = 0.0f, m3 = 0.0f;
    for (int u = b0 * blockDim.x + threadIdx.x; u < n16; u += nb * blockDim.x) {
        const float4* base = p + 4 * (size_t)u;
        float4 v0 = base[0], v1 = base[1], v2 = base[2], v3 = base[3];
        m0 = fmaxf(m0, fmaxf(fmaxf(fabsf(v0.x), fabsf(v0.y)),
                             fmaxf(fabsf(v0.z), fabsf(v0.w))));
        m1 = fmaxf(m1, fmaxf(fmaxf(fabsf(v1.x), fabsf(v1.y)),
                             fmaxf(fabsf(v1.z), fabsf(v1.w))));
        m2 = fmaxf(m2, fmaxf(fmaxf(fabsf(v2.x), fabsf(v2.y)),
                             fmaxf(fabsf(v2.z), fabsf(v2.w))));
        m3 = fmaxf(m3, fmaxf(fmaxf(fabsf(v3.x), fabsf(v3.y)),
                             fmaxf(fabsf(v3.z), fabsf(v3.w))));
    }
    float m = fmaxf(fmaxf(m0, m1), fmaxf(m2, m3));
    #pragma unroll
    for (int o = 16; o; o >>= 1)
        m = fmaxf(m, __shfl_xor_sync(0xFFFFFFFFu, m, o));
    if ((threadIdx.x & 31) == 0)
        atomicMax(&g_amax_bits[isX ? 0 : 1], __float_as_uint(m));
}

__global__ void compute_scales_kernel() {
    float sx = scale_from_bits(g_amax_bits[0]);
    float sw = scale_from_bits(g_amax_bits[1]);
    g_combined = (1.0f / sx) * (1.0f / sw);
}

__device__ __forceinline__ uint32_t q4_pack(float4 v, float s) {
    __nv_fp8x2_storage_t lo = __nv_cvt_float2_to_fp8x2(
        make_float2(v.x * s, v.y * s), __NV_SATFINITE, __NV_E4M3);
    __nv_fp8x2_storage_t hi = __nv_cvt_float2_to_fp8x2(
        make_float2(v.z * s, v.w * s), __NV_SATFINITE, __NV_E4M3);
    return (uint32_t)lo | ((uint32_t)hi << 16);
}

__global__ void quant_all_kernel(const float4* __restrict__ x, int nx16,
                                 const float4* __restrict__ w, int nw16,
                                 int xb) {
    const bool isX = (int)blockIdx.x < xb;
    const float4* in = isX ? x : w;
    const int n16 = isX ? nx16 : nw16;
    const int nb = isX ? xb : (gridDim.x - xb);
    const int b0 = isX ? (int)blockIdx.x : (int)blockIdx.x - xb;
    const float s = scale_from_bits(g_amax_bits[isX ? 0 : 1]);
    uint4* out = isX ? g_xq4 : g_wq4;

    for (int u = b0 * blockDim.x + threadIdx.x; u < n16; u += nb * blockDim.x) {
        const float4* base = in + 4 * (size_t)u;
        float4 v0 = base[0], v1 = base[1], v2 = base[2], v3 = base[3];
        out[u] = make_uint4(q4_pack(v0, s), q4_pack(v1, s),
                            q4_pack(v2, s), q4_pack(v3, s));
    }
}

// ============================================================================
// FP8 GEMM: CTA 128x64 (256 thr, 8 warps, warp tile 32x32), 4 CTAs/SM
// => 32 warps/SM (8/SMSP, architectural max).
// BK=64 stages: 192 rows x 64B = 12 KB; 4-stage ring = 48 KB/CTA.
// 64B-row swizzle seg^((row>>1)&3): 8 distinct granules per ldmatrix phase.
// ============================================================================

static constexpr int BM = 128;
static constexpr int BN = 64;
static constexpr int BK = 64;
static constexpr int STAGE_BYTES = (BM + BN) * BK;      // 12288
static constexpr int SMEM_TOTAL = 4 * STAGE_BYTES;      // 49152 (4 CTAs: 192 KB)

__global__ void __launch_bounds__(256, 4)
fp8_gemm_kernel(float* __restrict__ out, int M) {
    extern __shared__ char smem[];
    const uint32_t sbase = smem_to_u32(smem);

    const int tid = threadIdx.x;
    const int wid = tid >> 5;
    const int lane = tid & 31;
    const int wm = wid & 3;          // 4 warps along M
    const int wn = wid >> 2;         // 2 warps along N
    const int m0 = blockIdx.x * BM;
    const int n0 = blockIdx.y * BN;

    // ---- loader: 192 rows x 4 segs(16B) = 768 chunks; 3 per thread ----
    // chunk i: row = (tid>>2) + i*64 (i=0,1 -> A rows 0..127; i=2 -> B rows 0..63)
    // swizzle select (row>>1)&3 is constant = (tid>>3)&3 (i*64 keeps low bits)
    const int lrow = tid >> 2;                 // 0..63
    const int lseg = tid & 3;
    const uint32_t dsw = (uint32_t)((lseg ^ ((tid >> 3) & 3)) << 4);
    const uint32_t dst0 = (uint32_t)(lrow * 64) + dsw;     // + i*4096
    const char* srcA0 = (const char*)g_xq4 + (size_t)(m0 + lrow) * K_DIM + lseg * 16;
    const char* srcA1 = srcA0 + (size_t)64 * K_DIM;
    const char* srcB  = (const char*)g_wq4 + (size_t)(n0 + lrow) * K_DIM + lseg * 16;

    auto load_stage = [&](uint32_t stage_off, int kt) {
        const uint32_t st = sbase + stage_off + dst0;
        const int koff = kt * BK;
        CP_ASYNC_16(st,            srcA0 + koff);
        CP_ASYNC_16(st + 4096,     srcA1 + koff);
        CP_ASYNC_16(st + 8192,     srcB  + koff);
    };

    // ---- fragment addressing (64B rows) ----
    const int lm_g = lane >> 3;
    const int lm_r = lane & 7;
    const int lm_row_add = (lm_g & 1) * 8 + lm_r;
    const int lm_seg_add = lm_g >> 1;          // 0..1
    const int rsel = (lm_row_add >> 1) & 3;    // constant (base rows %16==0)

    uint32_t t_ks[2];
    #pragma unroll
    for (int ks = 0; ks < 2; ks++)
        t_ks[ks] = (uint32_t)(((2 * ks + lm_seg_add) ^ rsel) << 4);

    uint32_t offA[2], offB[2];
    #pragma unroll
    for (int mi = 0; mi < 2; mi++)
        offA[mi] = (uint32_t)((wm * 32 + mi * 16 + lm_row_add) * 64);
    #pragma unroll
    for (int np = 0; np < 2; np++)
        offB[np] = (uint32_t)(BM * 64 + (wn * 32 + np * 16 + lm_row_add) * 64);

    float acc[2][4][4];
    #pragma unroll
    for (int mi = 0; mi < 2; mi++)
        #pragma unroll
        for (int nj = 0; nj < 4; nj++)
            #pragma unroll
            for (int v = 0; v < 4; v++) acc[mi][nj][v] = 0.0f;

    constexpr int nkt = K_DIM / BK;   // 64

    auto step = [&](uint32_t stage_off, uint32_t next_off, int kt) {
        CP_WAIT(2);
        __syncthreads();
        if (kt + 3 < nkt) load_stage(next_off, kt + 3);
        CP_COMMIT();

        const uint32_t st = sbase + stage_off;

        #pragma unroll
        for (int ks = 0; ks < 2; ks++) {
            const uint32_t t = t_ks[ks];
            uint32_t a[2][4];
            #pragma unroll
            for (int mi = 0; mi < 2; mi++)
                LDMATRIX_X4(a[mi][0], a[mi][1], a[mi][2], a[mi][3],
                            st + offA[mi] + t);
            uint32_t b[4][2];
            #pragma unroll
            for (int np = 0; np < 2; np++) {
                uint32_t r0, r1, r2, r3;
                LDMATRIX_X4(r0, r1, r2, r3, st + offB[np] + t);
                b[2 * np][0] = r0;     b[2 * np][1] = r2;
                b[2 * np + 1][0] = r1; b[2 * np + 1][1] = r3;
            }
            #pragma unroll
            for (int mi = 0; mi < 2; mi++)
                #pragma unroll
                for (int nj = 0; nj < 4; nj++)
                    mma_e4m3(acc[mi][nj][0], acc[mi][nj][1],
                             acc[mi][nj][2], acc[mi][nj][3],
                             a[mi][0], a[mi][1], a[mi][2], a[mi][3],
                             b[nj][0], b[nj][1]);
        }
    };

    load_stage(0 * STAGE_BYTES, 0); CP_COMMIT();
    load_stage(1 * STAGE_BYTES, 1); CP_COMMIT();
    load_stage(2 * STAGE_BYTES, 2); CP_COMMIT();

    #pragma unroll 1
    for (int kt4 = 0; kt4 < nkt; kt4 += 4) {
        step(0 * STAGE_BYTES, 3 * STAGE_BYTES, kt4);
        step(1 * STAGE_BYTES, 0 * STAGE_BYTES, kt4 + 1);
        step(2 * STAGE_BYTES, 1 * STAGE_BYTES, kt4 + 2);
        step(3 * STAGE_BYTES, 2 * STAGE_BYTES, kt4 + 3);
    }

    // ---- epilogue: dequant, round through bf16, store fp32 ----
    const float cs = g_combined;
    const int r_quad = lane >> 2;
    const int c_pair = (lane & 3) * 2;
    #pragma unroll
    for (int mi = 0; mi < 2; mi++) {
        const int row_lo = m0 + wm * 32 + mi * 16 + r_quad;
        float* p_lo = out + (size_t)row_lo * N_DIM + n0 + wn * 32;
        float* p_hi = p_lo + (size_t)8 * N_DIM;
        #pragma unroll
        for (int nj = 0; nj < 4; nj++) {
            float2 v_lo = make_float2(
                __bfloat162float(__float2bfloat16(acc[mi][nj][0] * cs)),
                __bfloat162float(__float2bfloat16(acc[mi][nj][1] * cs)));
            float2 v_hi = make_float2(
                __bfloat162float(__float2bfloat16(acc[mi][nj][2] * cs)),
                __bfloat162float(__float2bfloat16(acc[mi][nj][3] * cs)));
            *(float2*)(p_lo + nj * 8 + c_pair) = v_lo;
            *(float2*)(p_hi + nj * 8 + c_pair) = v_hi;
        }
    }
}

// ============================================================================
// kernel_launch — 4 launches; GEMM at index 3 (the profiled slot)
// ============================================================================

extern "C" void kernel_launch(void* const* d_in, const int* in_sizes, int n_in,
                              void* d_out, int out_size) {
    const int M = out_size / N_DIM;                 // 8192
    const long nx_expect = (long)M * K_DIM;
    int xi = 0, wi = 1;
    if (n_in >= 2) {
        if ((long)in_sizes[1] == nx_expect && (long)in_sizes[0] != nx_expect) {
            xi = 1; wi = 0;
        }
    }
    const float* x = (const float*)d_in[xi];
    const float* w = (const float*)d_in[wi];
    float* out = (float*)d_out;

    const int nx16 = in_sizes[xi] / 16;
    const int nw16 = in_sizes[wi] / 16;

    cudaFuncSetAttribute(fp8_gemm_kernel,
                         cudaFuncAttributeMaxDynamicSharedMemorySize,
                         SMEM_TOTAL);

    void* amax_ptr = nullptr;
    cudaGetSymbolAddress(&amax_ptr, g_amax_bits);
    cudaMemsetAsync(amax_ptr, 0, 2 * sizeof(unsigned));

    absmax_all_kernel<<<1776, 256>>>((const float4*)x, nx16,
                                     (const float4*)w, nw16, 1184); // launch 0
    compute_scales_kernel<<<1, 1>>>();                              // launch 1
    quant_all_kernel<<<2664, 256>>>((const float4*)x, nx16,
                                    (const float4*)w, nw16, 1776);  // launch 2

    dim3 grid(M / BM, N_DIM / BN);
    fp8_gemm_kernel<<<grid, 256, SMEM_TOTAL>>>(out, M);             // launch 3
}

// round 17
// speedup vs baseline: 1.4528x; 1.4528x over previous
#include <cuda_runtime.h>
#include <cuda_bf16.h>
#include <cuda_fp8.h>
#include <cstdint>

// ============================================================================
// Base-ISA helpers
// ============================================================================

__device__ __forceinline__ uint32_t smem_to_u32(const void* smem_ptr) {
    uint32_t addr;
    asm("{ .reg .u64 tmp; cvta.to.shared.u64 tmp, %1; cvt.u32.u64 %0, tmp; }"
        : "=r"(addr) : "l"(smem_ptr));
    return addr;
}

#define CP_ASYNC_16(dst_u32, src_ptr) \
    asm volatile("cp.async.cg.shared.global [%0], [%1], 16;\n" \
                 :: "r"(dst_u32), "l"(src_ptr))

#define CP_COMMIT() asm volatile("cp.async.commit_group;\n" ::: "memory")

#define CP_WAIT(n)  asm volatile("cp.async.wait_group %0;\n" :: "n"(n) : "memory")

#define LDMATRIX_X4(r0, r1, r2, r3, addr) \
    asm volatile("ldmatrix.sync.aligned.m8n8.x4.shared.b16 {%0,%1,%2,%3}, [%4];\n" \
                 : "=r"(r0), "=r"(r1), "=r"(r2), "=r"(r3) : "r"(addr))

__device__ __forceinline__ void mma_e4m3(
    float& d0, float& d1, float& d2, float& d3,
    uint32_t a0, uint32_t a1, uint32_t a2, uint32_t a3,
    uint32_t b0, uint32_t b1)
{
    asm volatile(
        "mma.sync.aligned.m16n8k32.row.col.f32.e4m3.e4m3.f32 "
        "{%0,%1,%2,%3}, {%4,%5,%6,%7}, {%8,%9}, {%0,%1,%2,%3};\n"
        : "+f"(d0), "+f"(d1), "+f"(d2), "+f"(d3)
        : "r"(a0), "r"(a1), "r"(a2), "r"(a3), "r"(b0), "r"(b1));
}

// ============================================================================
// Problem constants & scratch
// ============================================================================

static constexpr int K_DIM = 4096;
static constexpr int N_DIM = 4096;
static constexpr int M_MAX = 8192;

__device__ uint4 g_xq4[(size_t)M_MAX * K_DIM / 16];   // 32 MB fp8 x
__device__ uint4 g_wq4[(size_t)N_DIM * K_DIM / 16];   // 16 MB fp8 w

__device__ unsigned g_amax_bits[2];   // [0]=x, [1]=w (cleared via memsetAsync)

__device__ __forceinline__ float scale_from_bits(unsigned bits) {
    float a = fmaxf(__uint_as_float(bits), 1e-12f);
    return 448.0f / a;
}

// ============================================================================
// Pre-pass kernels (2 launches; scales derived from g_amax_bits in-place)
// ============================================================================

__global__ void absmax_all_kernel(const float4* __restrict__ x, int nx16,
                                  const float4* __restrict__ w, int nw16,
                                  int xb) {
    const bool isX = (int)blockIdx.x < xb;
    const float4* p = isX ? x : w;
    const int n16 = isX ? nx16 : nw16;
    const int nb = isX ? xb : (gridDim.x - xb);
    const int b0 = isX ? (int)blockIdx.x : (int)blockIdx.x - xb;

    float m0 = 0.0f, m1 = 0.0f, m2 = 0.0f, m3 = 0.0f;
    for (int u = b0 * blockDim.x + threadIdx.x; u < n16; u += nb * blockDim.x) {
        const float4* base = p + 4 * (size_t)u;
        float4 v0 = base[0], v1 = base[1], v2 = base[2], v3 = base[3];
        m0 = fmaxf(m0, fmaxf(fmaxf(fabsf(v0.x), fabsf(v0.y)),
                             fmaxf(fabsf(v0.z), fabsf(v0.w))));
        m1 = fmaxf(m1, fmaxf(fmaxf(fabsf(v1.x), fabsf(v1.y)),
                             fmaxf(fabsf(v1.z), fabsf(v1.w))));
        m2 = fmaxf(m2, fmaxf(fmaxf(fabsf(v2.x), fabsf(v2.y)),
                             fmaxf(fabsf(v2.z), fabsf(v2.w))));
        m3 = fmaxf(m3, fmaxf(fmaxf(fabsf(v3.x), fabsf(v3.y)),
                             fmaxf(fabsf(v3.z), fabsf(v3.w))));
    }
    float m = fmaxf(fmaxf(m0, m1), fmaxf(m2, m3));
    #pragma unroll
    for (int o = 16; o; o >>= 1)
        m = fmaxf(m, __shfl_xor_sync(0xFFFFFFFFu, m, o));
    if ((threadIdx.x & 31) == 0)
        atomicMax(&g_amax_bits[isX ? 0 : 1], __float_as_uint(m));
}

__device__ __forceinline__ uint32_t q4_pack(float4 v, float s) {
    __nv_fp8x2_storage_t lo = __nv_cvt_float2_to_fp8x2(
        make_float2(v.x * s, v.y * s), __NV_SATFINITE, __NV_E4M3);
    __nv_fp8x2_storage_t hi = __nv_cvt_float2_to_fp8x2(
        make_float2(v.z * s, v.w * s), __NV_SATFINITE, __NV_E4M3);
    return (uint32_t)lo | ((uint32_t)hi << 16);
}

__global__ void quant_all_kernel(const float4* __restrict__ x, int nx16,
                                 const float4* __restrict__ w, int nw16,
                                 int xb) {
    const bool isX = (int)blockIdx.x < xb;
    const float4* in = isX ? x : w;
    const int n16 = isX ? nx16 : nw16;
    const int nb = isX ? xb : (gridDim.x - xb);
    const int b0 = isX ? (int)blockIdx.x : (int)blockIdx.x - xb;
    const float s = scale_from_bits(g_amax_bits[isX ? 0 : 1]);
    uint4* out = isX ? g_xq4 : g_wq4;

    for (int u = b0 * blockDim.x + threadIdx.x; u < n16; u += nb * blockDim.x) {
        const float4* base = in + 4 * (size_t)u;
        float4 v0 = base[0], v1 = base[1], v2 = base[2], v3 = base[3];
        out[u] = make_uint4(q4_pack(v0, s), q4_pack(v1, s),
                            q4_pack(v2, s), q4_pack(v3, s));
    }
}

// ============================================================================
// FP8 GEMM (R15 config — measured optimum):
// CTA 128x64, 256 threads (8 warps, warp tile 32x32), 3 CTAs/SM = 24 warps/SM,
// BK=128, 3-stage cp.async ring, single-buffered fragments.
// ============================================================================

static constexpr int BM = 128;
static constexpr int BN = 64;
static constexpr int BK = 128;
static constexpr int STAGE_BYTES = (BM + BN) * BK;      // 24 KB
static constexpr int SMEM_TOTAL = 3 * STAGE_BYTES;      // 72 KB (3 CTAs: 216 KB)

__global__ void __launch_bounds__(256, 3)
fp8_gemm_kernel(float* __restrict__ out, int M) {
    extern __shared__ char smem[];
    const uint32_t sbase = smem_to_u32(smem);

    const int tid = threadIdx.x;
    const int wid = tid >> 5;
    const int lane = tid & 31;
    const int wm = wid & 3;          // 4 warps along M (32 rows each)
    const int wn = wid >> 2;         // 2 warps along N (32 cols each)
    const int m0 = blockIdx.x * BM;
    const int n0 = blockIdx.y * BN;

    // ---- loader: 192 rows x 8 chunks / 256 threads = 6 chunks per thread ----
    const char* lsrc[6];
    uint32_t ldst[6];
    #pragma unroll
    for (int i = 0; i < 6; i++) {
        const int c = tid + i * 256;           // 0..1535
        const int row = c >> 3;                // 0..191
        const int seg = c & 7;
        ldst[i] = (uint32_t)(row * 128 + ((seg ^ (row & 7)) << 4));
        lsrc[i] = (row < BM
            ? (const char*)g_xq4 + (size_t)(m0 + row) * K_DIM
            : (const char*)g_wq4 + (size_t)(n0 + row - BM) * K_DIM) + seg * 16;
    }

    auto load_stage = [&](uint32_t stage_off, int kt) {
        const uint32_t st = sbase + stage_off;
        const int koff = kt * BK;
        #pragma unroll
        for (int i = 0; i < 6; i++)
            CP_ASYNC_16(st + ldst[i], lsrc[i] + koff);
    };

    // ---- fragment addressing ----
    const int lm_g = lane >> 3;
    const int lm_r = lane & 7;
    const int lm_row_add = (lm_g & 1) * 8 + lm_r;
    const int lm_seg_add = lm_g >> 1;

    uint32_t t_ks[4];
    #pragma unroll
    for (int ks = 0; ks < 4; ks++)
        t_ks[ks] = (uint32_t)(((2 * ks + lm_seg_add) ^ lm_r) << 4);

    uint32_t offA[2], offB[2];
    #pragma unroll
    for (int mi = 0; mi < 2; mi++)
        offA[mi] = (uint32_t)((wm * 32 + mi * 16 + lm_row_add) * 128);
    #pragma unroll
    for (int np = 0; np < 2; np++)
        offB[np] = (uint32_t)(BM * BK + (wn * 32 + np * 16 + lm_row_add) * 128);

    float acc[2][4][4];
    #pragma unroll
    for (int mi = 0; mi < 2; mi++)
        #pragma unroll
        for (int nj = 0; nj < 4; nj++)
            #pragma unroll
            for (int v = 0; v < 4; v++) acc[mi][nj][v] = 0.0f;

    constexpr int nkt = K_DIM / BK;   // 32

    auto step = [&](uint32_t stage_off, uint32_t next_off, int kt) {
        CP_WAIT(1);
        __syncthreads();
        if (kt + 2 < nkt) load_stage(next_off, kt + 2);
        CP_COMMIT();

        const uint32_t st = sbase + stage_off;

        #pragma unroll
        for (int ks = 0; ks < 4; ks++) {
            const uint32_t t = t_ks[ks];
            uint32_t a[2][4];
            #pragma unroll
            for (int mi = 0; mi < 2; mi++)
                LDMATRIX_X4(a[mi][0], a[mi][1], a[mi][2], a[mi][3],
                            st + offA[mi] + t);
            uint32_t b[4][2];
            #pragma unroll
            for (int np = 0; np < 2; np++) {
                uint32_t r0, r1, r2, r3;
                LDMATRIX_X4(r0, r1, r2, r3, st + offB[np] + t);
                b[2 * np][0] = r0;     b[2 * np][1] = r2;
                b[2 * np + 1][0] = r1; b[2 * np + 1][1] = r3;
            }
            #pragma unroll
            for (int mi = 0; mi < 2; mi++)
                #pragma unroll
                for (int nj = 0; nj < 4; nj++)
                    mma_e4m3(acc[mi][nj][0], acc[mi][nj][1],
                             acc[mi][nj][2], acc[mi][nj][3],
                             a[mi][0], a[mi][1], a[mi][2], a[mi][3],
                             b[nj][0], b[nj][1]);
        }
    };

    load_stage(0, 0); CP_COMMIT();
    load_stage(STAGE_BYTES, 1); CP_COMMIT();

    #pragma unroll 1
    for (int kt3 = 0; kt3 < 30; kt3 += 3) {
        step(0 * STAGE_BYTES, 2 * STAGE_BYTES, kt3);
        step(1 * STAGE_BYTES, 0 * STAGE_BYTES, kt3 + 1);
        step(2 * STAGE_BYTES, 1 * STAGE_BYTES, kt3 + 2);
    }
    step(0 * STAGE_BYTES, 2 * STAGE_BYTES, 30);
    step(1 * STAGE_BYTES, 0 * STAGE_BYTES, 31);

    // ---- epilogue: derive combined scale, dequant, round thru bf16, fp32 ----
    const float sx = scale_from_bits(g_amax_bits[0]);
    const float sw = scale_from_bits(g_amax_bits[1]);
    const float cs = (1.0f / sx) * (1.0f / sw);
    const int r_quad = lane >> 2;
    const int c_pair = (lane & 3) * 2;
    #pragma unroll
    for (int mi = 0; mi < 2; mi++) {
        const int row_lo = m0 + wm * 32 + mi * 16 + r_quad;
        float* p_lo = out + (size_t)row_lo * N_DIM + n0 + wn * 32;
        float* p_hi = p_lo + (size_t)8 * N_DIM;
        #pragma unroll
        for (int nj = 0; nj < 4; nj++) {
            float2 v_lo = make_float2(
                __bfloat162float(__float2bfloat16(acc[mi][nj][0] * cs)),
                __bfloat162float(__float2bfloat16(acc[mi][nj][1] * cs)));
            float2 v_hi = make_float2(
                __bfloat162float(__float2bfloat16(acc[mi][nj][2] * cs)),
                __bfloat162float(__float2bfloat16(acc[mi][nj][3] * cs)));
            *(float2*)(p_lo + nj * 8 + c_pair) = v_lo;
            *(float2*)(p_hi + nj * 8 + c_pair) = v_hi;
        }
    }
}

// ============================================================================
// kernel_launch — 3 kernel launches (absmax, quant, gemm)
// ============================================================================

extern "C" void kernel_launch(void* const* d_in, const int* in_sizes, int n_in,
                              void* d_out, int out_size) {
    const int M = out_size / N_DIM;                 // 8192
    const long nx_expect = (long)M * K_DIM;
    int xi = 0, wi = 1;
    if (n_in >= 2) {
        if ((long)in_sizes[1] == nx_expect && (long)in_sizes[0] != nx_expect) {
            xi = 1; wi = 0;
        }
    }
    const float* x = (const float*)d_in[xi];
    const float* w = (const float*)d_in[wi];
    float* out = (float*)d_out;

    const int nx16 = in_sizes[xi] / 16;
    const int nw16 = in_sizes[wi] / 16;

    cudaFuncSetAttribute(fp8_gemm_kernel,
                         cudaFuncAttributeMaxDynamicSharedMemorySize,
                         SMEM_TOTAL);

    void* amax_ptr = nullptr;
    cudaGetSymbolAddress(&amax_ptr, g_amax_bits);
    cudaMemsetAsync(amax_ptr, 0, 2 * sizeof(unsigned));

    absmax_all_kernel<<<1776, 256>>>((const float4*)x, nx16,
                                     (const float4*)w, nw16, 1184); // launch 0
    quant_all_kernel<<<2664, 256>>>((const float4*)x, nx16,
                                    (const float4*)w, nw16, 1776);  // launch 1

    dim3 grid(M / BM, N_DIM / BN);
    fp8_gemm_kernel<<<grid, 256, SMEM_TOTAL>>>(out, M);             // launch 2
}